// round 4
// baseline (speedup 1.0000x reference)
#include <cuda_runtime.h>
#include <cstdint>

#define CCH 64
#define HH 128
#define WW 128
#define NBATCH 32
#define KW 7
#define NTHREADS 256

#define XS2_STRIDE 148                  // float2 elements per ci row (>=146)
#define WS_ELEMS (KW * CCH * CCH)       // 28672 floats = 114688 B
#define XS2_ELEMS (CCH * XS2_STRIDE)    // 9472 float2  =  75776 B
#define SMEM_BYTES (WS_ELEMS * 4 + XS2_ELEMS * 8)   // 190464 B

__device__ __forceinline__ void ffma2(unsigned long long& d,
                                      unsigned long long a,
                                      unsigned long long b) {
    asm("fma.rn.f32x2 %0, %1, %2, %0;" : "+l"(d) : "l"(a), "l"(b));
}

__device__ __forceinline__ unsigned long long pack_dup(float x) {
    unsigned long long r;
    asm("mov.b64 %0, {%1, %1};" : "=l"(r) : "f"(x));
    return r;
}

__device__ __forceinline__ void unpack2(unsigned long long v, float& lo, float& hi) {
    asm("mov.b64 {%0, %1}, %2;" : "=f"(lo), "=f"(hi) : "l"(v));
}

extern "C" __global__ void __launch_bounds__(NTHREADS, 1)
fused_conv_roll_kernel(const float* __restrict__ x,
                       const float* __restrict__ wconv,
                       const float* __restrict__ p4,
                       float* __restrict__ out) {
    extern __shared__ unsigned char smem_raw[];
    float* Ws = (float*)smem_raw;                              // [j][ci][co]
    unsigned long long* xs2 =
        (unsigned long long*)(smem_raw + WS_ELEMS * 4);        // [ci][col] dup pairs

    const int tid = threadIdx.x;

    // Load + transpose weights once per persistent block.
    // global: wconv[co][ci][0][j] -> Ws[j][ci][co]
    for (int idx = tid; idx < WS_ELEMS; idx += NTHREADS) {
        int co  = idx / (CCH * KW);
        int rem = idx - co * (CCH * KW);
        int ci  = rem / KW;
        int j   = rem - ci * KW;
        Ws[(j * CCH + ci) * CCH + co] = wconv[idx];
    }
    const float p40 = p4[0], p41 = p4[1], p42 = p4[2];

    const int tw  = tid & 15;     // 16 threads along w
    const int tco = tid >> 4;     // 16 thread groups along co
    const int co0 = tco * 4;

    const int total_rows = NBATCH * HH;

    for (int row = blockIdx.x; row < total_rows; row += gridDim.x) {
        const int n = row >> 7;
        const int h = row & (HH - 1);

        __syncthreads();   // previous iter's reads of xs2 done

        // Stage x[n][:, h, :] into smem as DUPLICATED pairs, +/-9 zero pad
        {
            const float* xrow = x + ((size_t)(n * CCH) * HH + h) * WW;
            for (int idx = tid; idx < CCH * 146; idx += NTHREADS) {
                int ci  = idx / 146;
                int col = idx - ci * 146;
                int w   = col - 9;
                float v = (w >= 0 && w < WW) ? __ldg(xrow + (size_t)ci * (HH * WW) + w)
                                             : 0.0f;
                xs2[ci * XS2_STRIDE + col] = pack_dup(v);
            }
        }
        __syncthreads();

        // acc2[cp][e]: channels (co0+2cp, co0+2cp+1) packed, w = tw + 16*e
        unsigned long long acc2[2][8];
        #pragma unroll
        for (int cp = 0; cp < 2; ++cp)
            #pragma unroll
            for (int e = 0; e < 8; ++e) acc2[cp][e] = 0ULL;

        #pragma unroll
        for (int j = 0; j < KW; ++j) {
            const float* wsj = Ws + j * CCH * CCH + co0;
            // x storage col for output w at tap j: w + 3j
            const unsigned long long* xsb = xs2 + tw + 3 * j;
            #pragma unroll 4
            for (int ci = 0; ci < CCH; ++ci) {
                const ulonglong2 wv = *(const ulonglong2*)(wsj + ci * CCH);
                const unsigned long long* xr = xsb + ci * XS2_STRIDE;
                #pragma unroll
                for (int e = 0; e < 8; ++e) {
                    const unsigned long long xp = xr[16 * e];
                    ffma2(acc2[0][e], wv.x, xp);
                    ffma2(acc2[1][e], wv.y, xp);
                }
            }
        }

        // Epilogue: out = (x + t3) * t4
        // t4[h][w] = sum_k p4[k] * x[hm1 + 2k - 2][(w+2) mod W], h-taps zero-padded
        const int hm1 = (h - 1 + HH) & (HH - 1);
        const int r0 = hm1 - 2, r1 = hm1, r2 = hm1 + 2;
        const bool v0 = (r0 >= 0);
        const bool v2 = (r2 < HH);
        const float* xn = x + (size_t)n * CCH * HH * WW;
        float* outn = out + (size_t)n * CCH * HH * WW;

        #pragma unroll
        for (int cp = 0; cp < 2; ++cp) {
            #pragma unroll
            for (int half = 0; half < 2; ++half) {
                const int co = co0 + 2 * cp + half;
                const float* xc = xn + (size_t)co * HH * WW;
                float* oc = outn + ((size_t)co * HH + h) * WW;
                #pragma unroll
                for (int e = 0; e < 8; ++e) {
                    const int w  = tw + 16 * e;
                    const int wp = (w + 2) & (WW - 1);
                    float t4 = p41 * __ldg(xc + r1 * WW + wp);
                    if (v0) t4 = fmaf(p40, __ldg(xc + r0 * WW + wp), t4);
                    if (v2) t4 = fmaf(p42, __ldg(xc + r2 * WW + wp), t4);
                    float lo, hi;
                    unpack2(acc2[cp][e], lo, hi);
                    const float t3 = half ? hi : lo;
                    float xv_lo, xv_hi;
                    unpack2(xs2[co * XS2_STRIDE + w + 9], xv_lo, xv_hi);
                    oc[w] = (xv_lo + t3) * t4;
                }
            }
        }
    }
}

extern "C" void kernel_launch(void* const* d_in, const int* in_sizes, int n_in,
                              void* d_out, int out_size) {
    const float* x     = (const float*)d_in[0];
    const float* wconv = (const float*)d_in[1];
    const float* p4    = (const float*)d_in[2];
    float* out         = (float*)d_out;

    (void)in_sizes; (void)n_in; (void)out_size;

    cudaFuncSetAttribute(fused_conv_roll_kernel,
                         cudaFuncAttributeMaxDynamicSharedMemorySize, SMEM_BYTES);

    int dev = 0, sms = 148;
    cudaGetDevice(&dev);
    cudaDeviceGetAttribute(&sms, cudaDevAttrMultiProcessorCount, dev);

    fused_conv_roll_kernel<<<sms, NTHREADS, SMEM_BYTES>>>(x, wconv, p4, out);
}

// round 7
// speedup vs baseline: 1.3305x; 1.3305x over previous
#include <cuda_runtime.h>
#include <cstdint>

#define CCH 64
#define HH 128
#define WW 128
#define NBATCH 32
#define KW 7
#define NTHREADS 128
#define TOTAL_ROWS (NBATCH * HH)

// smem layout (bytes)
#define BOFF 0
#define B_BYTES (KW * 8 * 4 * 32 * 16)        // 114688: [j][kt][ntp][lane] uint4
#define TOFF B_BYTES
#define T_STRIDE 68                            // uint32 per T row (64 ci + 4 pad)
#define T_ROWS 152                             // rows 0..145 used (w+9 + 3j), pad to 152
#define TBUF_BYTES (T_ROWS * T_STRIDE * 4)     // 41344
#define SMEM_DYN (B_BYTES + 2 * TBUF_BYTES)    // 197376

__device__ __forceinline__ uint32_t f2tf32(float f) {
    uint32_t r;
    asm("cvt.rna.tf32.f32 %0, %1;" : "=r"(r) : "f"(f));
    return r;
}

__device__ __forceinline__ void mma_tf32(float* d,
                                         uint32_t a0, uint32_t a1,
                                         uint32_t a2, uint32_t a3,
                                         uint32_t b0, uint32_t b1) {
    asm volatile(
        "mma.sync.aligned.m16n8k8.row.col.f32.tf32.tf32.f32 "
        "{%0,%1,%2,%3}, {%4,%5,%6,%7}, {%8,%9}, {%0,%1,%2,%3};"
        : "+f"(d[0]), "+f"(d[1]), "+f"(d[2]), "+f"(d[3])
        : "r"(a0), "r"(a1), "r"(a2), "r"(a3), "r"(b0), "r"(b1));
}

// Stage x[n][:, h, :] -> T[buf] as tf32, transposed [w+9][ci].
__device__ __forceinline__ void stage_T(char* smem, const float* __restrict__ x,
                                        int n, int h, int buf) {
    const int tid = threadIdx.x;
    uint32_t* Tb = (uint32_t*)(smem + TOFF + buf * TBUF_BYTES);
    const float* xrow = x + ((size_t)(n * CCH) * HH + h) * WW;
    const int ci = tid & 63;
    #pragma unroll
    for (int it = 0; it < 16; ++it) {
        const int wg = (tid >> 6) + 2 * it;          // 0..31, 4 w per wg
        const float4 v = __ldg((const float4*)(xrow + (size_t)ci * (HH * WW) + wg * 4));
        uint32_t* dst = Tb + (4 * wg + 9) * T_STRIDE + ci;
        dst[0 * T_STRIDE] = f2tf32(v.x);
        dst[1 * T_STRIDE] = f2tf32(v.y);
        dst[2 * T_STRIDE] = f2tf32(v.z);
        dst[3 * T_STRIDE] = f2tf32(v.w);
    }
}

extern "C" __global__ void __launch_bounds__(NTHREADS, 1)
fused_conv_mma_kernel(const float* __restrict__ x,
                      const float* __restrict__ wconv,
                      const float* __restrict__ p4,
                      float* __restrict__ out) {
    extern __shared__ char smem[];
    const int tid = threadIdx.x;
    const int lane = tid & 31;
    const int warp = tid >> 5;

    // ---- one-time: pack B fragments [j][kt][ntp][lane] = uint4 ----
    // b-frag (col-major k8n8): thread t holds B[k=t%4][n=t/4], B[k=t%4+4][n=t/4]
    for (int idx = tid; idx < KW * 8 * 4 * 32; idx += NTHREADS) {
        const int t   = idx & 31;
        const int ntp = (idx >> 5) & 3;
        const int kt  = (idx >> 7) & 7;
        const int j   = idx >> 10;
        const int n_in = t >> 2;
        const int k_in = t & 3;
        const int ci0 = kt * 8 + k_in, ci1 = ci0 + 4;
        const int coA = (2 * ntp) * 8 + n_in, coB = coA + 8;
        uint4 v;
        v.x = f2tf32(__ldg(wconv + (coA * CCH + ci0) * KW + j));
        v.y = f2tf32(__ldg(wconv + (coA * CCH + ci1) * KW + j));
        v.z = f2tf32(__ldg(wconv + (coB * CCH + ci0) * KW + j));
        v.w = f2tf32(__ldg(wconv + (coB * CCH + ci1) * KW + j));
        ((uint4*)(smem + BOFF))[idx] = v;
    }
    // zero T (pad rows stay zero forever)
    for (int i = tid; i < 2 * T_ROWS * T_STRIDE; i += NTHREADS)
        ((uint32_t*)(smem + TOFF))[i] = 0;

    const float p40 = __ldg(p4 + 0), p41 = __ldg(p4 + 1), p42 = __ldg(p4 + 2);

    int row = blockIdx.x;
    __syncthreads();
    if (row < TOTAL_ROWS) stage_T(smem, x, row >> 7, row & (HH - 1), 0);
    __syncthreads();

    int buf = 0;
    const uint4* Bfr = (const uint4*)(smem + BOFF);

    while (row < TOTAL_ROWS) {
        const int n = row >> 7;
        const int h = row & (HH - 1);

        // ---- MMA: out[w][co] = sum_{j,ci} T[w+3j][ci] * Wj[co][ci] ----
        float acc[2][8][4];
        #pragma unroll
        for (int mt = 0; mt < 2; ++mt)
            #pragma unroll
            for (int nt = 0; nt < 8; ++nt)
                #pragma unroll
                for (int q = 0; q < 4; ++q) acc[mt][nt][q] = 0.0f;

        const uint32_t* Tb = (const uint32_t*)(smem + TOFF + buf * TBUF_BYTES);
        const int rbase = warp * 32 + (lane >> 2);
        const int cbase = lane & 3;

        #pragma unroll 1
        for (int j = 0; j < KW; ++j) {
            const uint32_t* Trow = Tb + (rbase + 3 * j) * T_STRIDE + cbase;
            const uint4* Bj = Bfr + j * 1024 + lane;
            #pragma unroll
            for (int kt = 0; kt < 8; ++kt) {
                const uint32_t* Tc = Trow + kt * 8;
                const uint32_t a0 = Tc[0];
                const uint32_t a1 = Tc[8 * T_STRIDE];
                const uint32_t a2 = Tc[4];
                const uint32_t a3 = Tc[8 * T_STRIDE + 4];
                const uint32_t a4 = Tc[16 * T_STRIDE];
                const uint32_t a5 = Tc[24 * T_STRIDE];
                const uint32_t a6 = Tc[16 * T_STRIDE + 4];
                const uint32_t a7 = Tc[24 * T_STRIDE + 4];
                const uint4 b01 = Bj[kt * 128 + 0 * 32];
                const uint4 b23 = Bj[kt * 128 + 1 * 32];
                const uint4 b45 = Bj[kt * 128 + 2 * 32];
                const uint4 b67 = Bj[kt * 128 + 3 * 32];
                mma_tf32(acc[0][0], a0, a1, a2, a3, b01.x, b01.y);
                mma_tf32(acc[0][1], a0, a1, a2, a3, b01.z, b01.w);
                mma_tf32(acc[0][2], a0, a1, a2, a3, b23.x, b23.y);
                mma_tf32(acc[0][3], a0, a1, a2, a3, b23.z, b23.w);
                mma_tf32(acc[0][4], a0, a1, a2, a3, b45.x, b45.y);
                mma_tf32(acc[0][5], a0, a1, a2, a3, b45.z, b45.w);
                mma_tf32(acc[0][6], a0, a1, a2, a3, b67.x, b67.y);
                mma_tf32(acc[0][7], a0, a1, a2, a3, b67.z, b67.w);
                mma_tf32(acc[1][0], a4, a5, a6, a7, b01.x, b01.y);
                mma_tf32(acc[1][1], a4, a5, a6, a7, b01.z, b01.w);
                mma_tf32(acc[1][2], a4, a5, a6, a7, b23.x, b23.y);
                mma_tf32(acc[1][3], a4, a5, a6, a7, b23.z, b23.w);
                mma_tf32(acc[1][4], a4, a5, a6, a7, b45.x, b45.y);
                mma_tf32(acc[1][5], a4, a5, a6, a7, b45.z, b45.w);
                mma_tf32(acc[1][6], a4, a5, a6, a7, b67.x, b67.y);
                mma_tf32(acc[1][7], a4, a5, a6, a7, b67.z, b67.w);
            }
        }

        // ---- overlap: stage next row into other buffer ----
        const int nrow = row + gridDim.x;
        if (nrow < TOTAL_ROWS)
            stage_T(smem, x, nrow >> 7, nrow & (HH - 1), buf ^ 1);

        // ---- epilogue: out = (x + t3) * t4 ----
        {
            const int hm1 = (h - 1 + HH) & (HH - 1);
            const int r0 = hm1 - 2, r2 = hm1 + 2;
            const bool has0 = (r0 >= 0), has2 = (r2 < HH);
            const float* xb = x + (size_t)n * CCH * HH * WW;
            float* ob = out + (size_t)n * CCH * HH * WW;
            #pragma unroll
            for (int mt = 0; mt < 2; ++mt) {
                #pragma unroll
                for (int half = 0; half < 2; ++half) {
                    const int w = warp * 32 + mt * 16 + (lane >> 2) + half * 8;
                    const int wp = (w + 2) & (WW - 1);
                    #pragma unroll
                    for (int nt = 0; nt < 8; ++nt) {
                        #pragma unroll
                        for (int q = 0; q < 2; ++q) {
                            const int co = nt * 8 + 2 * (lane & 3) + q;
                            const float* xc = xb + (size_t)co * (HH * WW);
                            float t4 = p41 * __ldg(xc + hm1 * WW + wp);
                            if (has0) t4 = fmaf(p40, __ldg(xc + r0 * WW + wp), t4);
                            if (has2) t4 = fmaf(p42, __ldg(xc + r2 * WW + wp), t4);
                            const float xv = __ldg(xc + h * WW + w);
                            ob[(size_t)co * (HH * WW) + h * WW + w] =
                                (xv + acc[mt][nt][half * 2 + q]) * t4;
                        }
                    }
                }
            }
        }

        __syncthreads();   // T[buf] reads done everywhere; T[buf^1] stage visible
        buf ^= 1;
        row = nrow;
    }
}

extern "C" void kernel_launch(void* const* d_in, const int* in_sizes, int n_in,
                              void* d_out, int out_size) {
    const float* x     = (const float*)d_in[0];
    const float* wconv = (const float*)d_in[1];
    const float* p4    = (const float*)d_in[2];
    float* out         = (float*)d_out;

    (void)in_sizes; (void)n_in; (void)out_size;

    cudaFuncSetAttribute(fused_conv_mma_kernel,
                         cudaFuncAttributeMaxDynamicSharedMemorySize, SMEM_DYN);

    int dev = 0, sms = 148;
    cudaGetDevice(&dev);
    cudaDeviceGetAttribute(&sms, cudaDevAttrMultiProcessorCount, dev);

    fused_conv_mma_kernel<<<sms, NTHREADS, SMEM_DYN>>>(x, wconv, p4, out);
}

// round 8
// speedup vs baseline: 2.0743x; 1.5591x over previous
#include <cuda_runtime.h>
#include <cstdint>

#define CCH 64
#define HH 128
#define WW 128
#define NBATCH 32
#define KW 7
#define NTHREADS 256
#define TOTAL_ROWS (NBATCH * HH)
#define HW (HH * WW)

// smem layout (bytes)
#define B_BYTES (KW * 8 * 4 * 32 * 16)        // 114688: [j][kt][ntp][lane] uint4
#define TOFF B_BYTES
#define T_STRIDE 68                            // uint32 per T row (64 ci + 4 pad)
#define T_ROWS 152
#define T_BYTES (T_ROWS * T_STRIDE * 4)        // 41344
#define CONVOFF (TOFF + T_BYTES)
#define BUF_STRIDE 132                         // floats per co row (128 + 4 pad)
#define BUF_BYTES (CCH * BUF_STRIDE * 4)       // 33792
#define T4OFF (CONVOFF + BUF_BYTES)
#define SMEM_DYN (T4OFF + BUF_BYTES)           // 223616

__device__ __forceinline__ uint32_t f2tf32(float f) {
    uint32_t r;
    asm("cvt.rna.tf32.f32 %0, %1;" : "=r"(r) : "f"(f));
    return r;
}

__device__ __forceinline__ void mma_tf32(float* d,
                                         uint32_t a0, uint32_t a1,
                                         uint32_t a2, uint32_t a3,
                                         uint32_t b0, uint32_t b1) {
    asm volatile(
        "mma.sync.aligned.m16n8k8.row.col.f32.tf32.tf32.f32 "
        "{%0,%1,%2,%3}, {%4,%5,%6,%7}, {%8,%9}, {%0,%1,%2,%3};"
        : "+f"(d[0]), "+f"(d[1]), "+f"(d[2]), "+f"(d[3])
        : "r"(a0), "r"(a1), "r"(a2), "r"(a3), "r"(b0), "r"(b1));
}

// Stage x[n][:, h, :] -> T as tf32, transposed [w+9][ci].
__device__ __forceinline__ void stage_T(char* smem, const float* __restrict__ x,
                                        int n, int h) {
    const int tid = threadIdx.x;
    uint32_t* Tb = (uint32_t*)(smem + TOFF);
    const float* xrow = x + ((size_t)(n * CCH) * HH + h) * WW;
    const int ci = tid & 63;
    const int w0 = tid >> 6;                       // 0..3
    #pragma unroll
    for (int it = 0; it < 8; ++it) {
        const int wg = w0 + 4 * it;                // 0..31
        const float4 v = __ldg((const float4*)(xrow + (size_t)ci * HW + wg * 4));
        uint32_t* dst = Tb + (4 * wg + 9) * T_STRIDE + ci;
        dst[0 * T_STRIDE] = f2tf32(v.x);
        dst[1 * T_STRIDE] = f2tf32(v.y);
        dst[2 * T_STRIDE] = f2tf32(v.z);
        dst[3 * T_STRIDE] = f2tf32(v.w);
    }
}

extern "C" __global__ void __launch_bounds__(NTHREADS, 1)
fused_conv_mma_kernel(const float* __restrict__ x,
                      const float* __restrict__ wconv,
                      const float* __restrict__ p4,
                      float* __restrict__ out) {
    extern __shared__ char smem[];
    const int tid = threadIdx.x;
    const int lane = tid & 31;
    const int warp = tid >> 5;
    const int g = warp >> 2;          // n-half (0: co 0..31, 1: co 32..63)
    const int mwarp = warp & 3;       // m-stripe (32 w rows)

    // ---- one-time: pack B fragments [j][kt][ntp][lane] = uint4 ----
    for (int idx = tid; idx < KW * 8 * 4 * 32; idx += NTHREADS) {
        const int t   = idx & 31;
        const int ntp = (idx >> 5) & 3;
        const int kt  = (idx >> 7) & 7;
        const int j   = idx >> 10;
        const int n_in = t >> 2;
        const int k_in = t & 3;
        const int ci0 = kt * 8 + k_in, ci1 = ci0 + 4;
        const int coA = 16 * ntp + n_in, coB = coA + 8;
        uint4 v;
        v.x = f2tf32(__ldg(wconv + (coA * CCH + ci0) * KW + j));
        v.y = f2tf32(__ldg(wconv + (coA * CCH + ci1) * KW + j));
        v.z = f2tf32(__ldg(wconv + (coB * CCH + ci0) * KW + j));
        v.w = f2tf32(__ldg(wconv + (coB * CCH + ci1) * KW + j));
        ((uint4*)smem)[idx] = v;
    }
    // zero T (pad rows stay zero forever)
    for (int i = tid; i < T_ROWS * T_STRIDE; i += NTHREADS)
        ((uint32_t*)(smem + TOFF))[i] = 0;

    const float p40 = __ldg(p4 + 0), p41 = __ldg(p4 + 1), p42 = __ldg(p4 + 2);

    __syncthreads();
    int row = blockIdx.x;
    if (row < TOTAL_ROWS) stage_T(smem, x, row >> 7, row & (HH - 1));
    __syncthreads();

    const uint4* Bfr = (const uint4*)smem;
    float* convbuf = (float*)(smem + CONVOFF);
    float* t4buf   = (float*)(smem + T4OFF);

    while (row < TOTAL_ROWS) {
        const int n = row >> 7;
        const int h = row & (HH - 1);
        const float* xb = x + (size_t)n * CCH * HW;
        float* ob = out + (size_t)n * CCH * HW;
        const int hm1 = (h - 1 + HH) & (HH - 1);
        const int r0 = hm1 - 2, r2 = hm1 + 2;
        const bool has0 = (r0 >= 0), has2 = (r2 < HH);

        // ---- MMA: conv[w][co] for co-half g, m-stripe mwarp ----
        float acc[2][4][4];
        #pragma unroll
        for (int mt = 0; mt < 2; ++mt)
            #pragma unroll
            for (int nt = 0; nt < 4; ++nt)
                #pragma unroll
                for (int q = 0; q < 4; ++q) acc[mt][nt][q] = 0.0f;

        {
            const uint32_t* Tb = (const uint32_t*)(smem + TOFF);
            const int rbase = mwarp * 32 + (lane >> 2);
            const int cbase = lane & 3;
            #pragma unroll 1
            for (int j = 0; j < KW; ++j) {
                const uint32_t* Trow = Tb + (rbase + 3 * j) * T_STRIDE + cbase;
                const uint4* Bj = Bfr + j * 1024 + 64 * g + lane;
                #pragma unroll
                for (int kt = 0; kt < 8; ++kt) {
                    const uint32_t* Tc = Trow + kt * 8;
                    const uint32_t a0 = Tc[0];
                    const uint32_t a1 = Tc[8 * T_STRIDE];
                    const uint32_t a2 = Tc[4];
                    const uint32_t a3 = Tc[8 * T_STRIDE + 4];
                    const uint32_t a4 = Tc[16 * T_STRIDE];
                    const uint32_t a5 = Tc[24 * T_STRIDE];
                    const uint32_t a6 = Tc[16 * T_STRIDE + 4];
                    const uint32_t a7 = Tc[24 * T_STRIDE + 4];
                    const uint4 b01 = Bj[kt * 128];
                    const uint4 b23 = Bj[kt * 128 + 32];
                    mma_tf32(acc[0][0], a0, a1, a2, a3, b01.x, b01.y);
                    mma_tf32(acc[0][1], a0, a1, a2, a3, b01.z, b01.w);
                    mma_tf32(acc[0][2], a0, a1, a2, a3, b23.x, b23.y);
                    mma_tf32(acc[0][3], a0, a1, a2, a3, b23.z, b23.w);
                    mma_tf32(acc[1][0], a4, a5, a6, a7, b01.x, b01.y);
                    mma_tf32(acc[1][1], a4, a5, a6, a7, b01.z, b01.w);
                    mma_tf32(acc[1][2], a4, a5, a6, a7, b23.x, b23.y);
                    mma_tf32(acc[1][3], a4, a5, a6, a7, b23.z, b23.w);
                }
            }
        }

        // ---- dump accumulators to convbuf[co][w] (conflict-free) ----
        #pragma unroll
        for (int mt = 0; mt < 2; ++mt)
            #pragma unroll
            for (int half = 0; half < 2; ++half) {
                const int w = mwarp * 32 + mt * 16 + (lane >> 2) + half * 8;
                #pragma unroll
                for (int nt = 0; nt < 4; ++nt)
                    #pragma unroll
                    for (int q = 0; q < 2; ++q) {
                        const int co = 32 * g + nt * 8 + 2 * (lane & 3) + q;
                        convbuf[co * BUF_STRIDE + w] = acc[mt][nt][half * 2 + q];
                    }
            }

        // ---- cooperative t4 into t4buf[co][w] (coalesced LDG) ----
        #pragma unroll 1
        for (int i = 0; i < 8; ++i) {
            const int co = warp + 8 * i;
            const float* xc = xb + (size_t)co * HW;
            #pragma unroll
            for (int k = 0; k < 4; ++k) {
                const int win = lane + 32 * k;
                float t4v = p41 * __ldg(xc + hm1 * WW + win);
                if (has0) t4v = fmaf(p40, __ldg(xc + r0 * WW + win), t4v);
                if (has2) t4v = fmaf(p42, __ldg(xc + r2 * WW + win), t4v);
                t4buf[co * BUF_STRIDE + ((win - 2) & (WW - 1))] = t4v;
            }
        }

        __syncthreads();

        // ---- stage next row (overlaps out-phase latency) ----
        const int nrow = row + gridDim.x;
        if (nrow < TOTAL_ROWS) stage_T(smem, x, nrow >> 7, nrow & (HH - 1));

        // ---- out phase: coalesced float4 ----
        #pragma unroll 1
        for (int i = 0; i < 8; ++i) {
            const int co = warp + 8 * i;
            const float4 cv = *(const float4*)(convbuf + co * BUF_STRIDE + 4 * lane);
            const float4 tv = *(const float4*)(t4buf + co * BUF_STRIDE + 4 * lane);
            const float4 xv = __ldg((const float4*)(xb + (size_t)co * HW + h * WW + 4 * lane));
            float4 ov;
            ov.x = (xv.x + cv.x) * tv.x;
            ov.y = (xv.y + cv.y) * tv.y;
            ov.z = (xv.z + cv.z) * tv.z;
            ov.w = (xv.w + cv.w) * tv.w;
            *(float4*)(ob + (size_t)co * HW + h * WW + 4 * lane) = ov;
        }

        __syncthreads();   // T staged + convbuf/t4buf reads done
        row = nrow;
    }
}

extern "C" void kernel_launch(void* const* d_in, const int* in_sizes, int n_in,
                              void* d_out, int out_size) {
    const float* x     = (const float*)d_in[0];
    const float* wconv = (const float*)d_in[1];
    const float* p4    = (const float*)d_in[2];
    float* out         = (float*)d_out;

    (void)in_sizes; (void)n_in; (void)out_size;

    cudaFuncSetAttribute(fused_conv_mma_kernel,
                         cudaFuncAttributeMaxDynamicSharedMemorySize, SMEM_DYN);

    int dev = 0, sms = 148;
    cudaGetDevice(&dev);
    cudaDeviceGetAttribute(&sms, cudaDevAttrMultiProcessorCount, dev);

    fused_conv_mma_kernel<<<sms, NTHREADS, SMEM_DYN>>>(x, wconv, p4, out);
}